// round 2
// baseline (speedup 1.0000x reference)
#include <cuda_runtime.h>
#include <cstdint>

// out[b,n] = sum_{c,hw} x[b,c,hw] * W_s[n,hw] * W_d[n,c] + W_b[n]
// Stage 1: Y[(b*C+c), n] = x_row . W_s_row   (M=8192, N=1024, K=3136) via tf32 mma.sync
// Stage 2: out[b,n] = sum_c Y[(b,c),n] * W_d[n,c] + W_b[n]

#define M_DIM 8192
#define N_DIM 1024
#define K_DIM 3136
#define BM 128
#define BN 128
#define BK 16
#define LDSS 20   // BK + 4 pad -> conflict-free fragment LDS

__device__ float g_Y[(size_t)M_DIM * N_DIM];  // 33.5 MB scratch (static, no alloc)

__device__ __forceinline__ void cp_async16(void* s, const void* g) {
    uint32_t sa = (uint32_t)__cvta_generic_to_shared(s);
    asm volatile("cp.async.cg.shared.global [%0], [%1], 16;\n" :: "r"(sa), "l"(g));
}
__device__ __forceinline__ uint32_t f2tf32(float f) {
    uint32_t u;
    asm("cvt.rna.tf32.f32 %0, %1;" : "=r"(u) : "f"(f));
    return u;
}

__global__ __launch_bounds__(256, 2)
void gemm_tf32(const float* __restrict__ A, const float* __restrict__ B) {
    __shared__ float As[2][BM][LDSS];
    __shared__ float Bs[2][BN][LDSS];

    const int tid  = threadIdx.x;
    const int bn   = blockIdx.x;   // 0..7
    const int bm   = blockIdx.y;   // 0..63
    const int warp = tid >> 5;
    const int lane = tid & 31;
    const int wm   = warp & 3;     // 4 warps along M (32 rows each)
    const int wn   = warp >> 2;    // 2 warps along N (64 cols each)
    const int g    = lane >> 2;    // groupID 0..7
    const int t4   = lane & 3;     // threadID_in_group 0..3

    const float* Ab = A + (size_t)(bm * BM) * K_DIM;
    const float* Bb = B + (size_t)(bn * BN) * K_DIM;
    const int lr = tid >> 2;        // 0..63 (row within tile half)
    const int lc = (tid & 3) * 4;   // 0,4,8,12 (float4 offset in K)

    float acc[2][8][4];
    #pragma unroll
    for (int i = 0; i < 2; i++)
        #pragma unroll
        for (int j = 0; j < 8; j++)
            #pragma unroll
            for (int k = 0; k < 4; k++) acc[i][j][k] = 0.f;

    auto load_stage = [&](int buf, int kt) {
        const float* ap = Ab + (size_t)lr * K_DIM + kt * BK + lc;
        const float* bp = Bb + (size_t)lr * K_DIM + kt * BK + lc;
        cp_async16(&As[buf][lr][lc],      ap);
        cp_async16(&As[buf][lr + 64][lc], ap + (size_t)64 * K_DIM);
        cp_async16(&Bs[buf][lr][lc],      bp);
        cp_async16(&Bs[buf][lr + 64][lc], bp + (size_t)64 * K_DIM);
    };

    load_stage(0, 0);
    asm volatile("cp.async.commit_group;\n" ::: "memory");

    const int NT = K_DIM / BK;  // 196
    for (int kt = 0; kt < NT; ++kt) {
        if (kt + 1 < NT) {
            load_stage((kt + 1) & 1, kt + 1);
            asm volatile("cp.async.commit_group;\n" ::: "memory");
            asm volatile("cp.async.wait_group 1;\n" ::: "memory");
        } else {
            asm volatile("cp.async.wait_group 0;\n" ::: "memory");
        }
        __syncthreads();

        const int buf = kt & 1;
        #pragma unroll
        for (int kk = 0; kk < BK; kk += 8) {
            // A fragments: m16n8k8 tf32 layout (a0..a3)
            uint32_t af[2][4];
            #pragma unroll
            for (int mi = 0; mi < 2; mi++) {
                int r = wm * 32 + mi * 16 + g;
                af[mi][0] = f2tf32(As[buf][r][kk + t4]);
                af[mi][1] = f2tf32(As[buf][r + 8][kk + t4]);
                af[mi][2] = f2tf32(As[buf][r][kk + t4 + 4]);
                af[mi][3] = f2tf32(As[buf][r + 8][kk + t4 + 4]);
            }
            // B fragments: b0 = B[k=t4][n=g], b1 = B[k=t4+4][n=g]; Bs stored [n][k]
            uint32_t bf[8][2];
            #pragma unroll
            for (int ni = 0; ni < 8; ni++) {
                int c = wn * 64 + ni * 8 + g;
                bf[ni][0] = f2tf32(Bs[buf][c][kk + t4]);
                bf[ni][1] = f2tf32(Bs[buf][c][kk + t4 + 4]);
            }
            #pragma unroll
            for (int mi = 0; mi < 2; mi++)
                #pragma unroll
                for (int ni = 0; ni < 8; ni++) {
                    asm volatile(
                        "mma.sync.aligned.m16n8k8.row.col.f32.tf32.tf32.f32 "
                        "{%0,%1,%2,%3}, {%4,%5,%6,%7}, {%8,%9}, {%0,%1,%2,%3};\n"
                        : "+f"(acc[mi][ni][0]), "+f"(acc[mi][ni][1]),
                          "+f"(acc[mi][ni][2]), "+f"(acc[mi][ni][3])
                        : "r"(af[mi][0]), "r"(af[mi][1]), "r"(af[mi][2]), "r"(af[mi][3]),
                          "r"(bf[ni][0]), "r"(bf[ni][1]));
                }
        }
        __syncthreads();
    }

    // Epilogue: c0,c1 at (row=g, col=t4*2), c2,c3 at (row=g+8, col=t4*2)
    #pragma unroll
    for (int mi = 0; mi < 2; mi++) {
        int r0 = bm * BM + wm * 32 + mi * 16 + g;
        #pragma unroll
        for (int ni = 0; ni < 8; ni++) {
            int c0 = bn * BN + wn * 64 + ni * 8 + t4 * 2;
            float2* p0 = reinterpret_cast<float2*>(&g_Y[(size_t)r0 * N_DIM + c0]);
            float2* p1 = reinterpret_cast<float2*>(&g_Y[(size_t)(r0 + 8) * N_DIM + c0]);
            *p0 = make_float2(acc[mi][ni][0], acc[mi][ni][1]);
            *p1 = make_float2(acc[mi][ni][2], acc[mi][ni][3]);
        }
    }
}

__global__ __launch_bounds__(1024)
void reduce_k(const float* __restrict__ Wd, const float* __restrict__ Wb,
              float* __restrict__ out) {
    const int b = blockIdx.x;     // 0..31
    const int n = threadIdx.x;    // 0..1023
    const float* y  = g_Y + (size_t)b * 256 * N_DIM + n;  // stride N_DIM over c, coalesced in n
    const float* wd = Wd + n * 256;
    float acc = 0.f;
    #pragma unroll 8
    for (int c = 0; c < 256; c++)
        acc += y[(size_t)c * N_DIM] * wd[c];
    out[b * N_DIM + n] = acc + Wb[n];
}

extern "C" void kernel_launch(void* const* d_in, const int* in_sizes, int n_in,
                              void* d_out, int out_size) {
    const float* x  = (const float*)d_in[0];  // (32,256,56,56)  = [8192 x 3136]
    const float* Ws = (const float*)d_in[1];  // (1024,56,56)    = [1024 x 3136]
    const float* Wd = (const float*)d_in[2];  // (1024,256,1,1)  = [1024 x 256]
    const float* Wb = (const float*)d_in[3];  // (1,1024)
    float* out = (float*)d_out;               // (32,1024) fp32

    dim3 grid(N_DIM / BN, M_DIM / BM);        // (8, 64)
    gemm_tf32<<<grid, 256>>>(x, Ws);
    reduce_k<<<32, 1024>>>(Wd, Wb, out);
}

// round 5
// speedup vs baseline: 1.1992x; 1.1992x over previous
#include <cuda_runtime.h>
#include <cstdint>

// out[b,n] = sum_{c,hw} x[b,c,hw] * W_s[n,hw] * W_d[n,c] + W_b[n]
// Single fused kernel: tf32 mma.sync GEMM D[(b,c),n] = x . Ws^T with epilogue
// out[b,n] += sum_rows D * Wd  (out pre-initialized to W_b).

#define M_DIM 8192
#define N_DIM 1024
#define K_DIM 3136
#define BM 128
#define BN 256
#define BK 16
#define STAGES 3
#define LDSS 20                          // padded row stride (floats)
#define A_ST_FL (BM * LDSS)              // 2560 floats
#define B_ST_FL (BN * LDSS)              // 5120 floats
#define ST_FL   (A_ST_FL + B_ST_FL)      // 7680 floats = 30720 B
#define SMEM_BYTES (STAGES * ST_FL * 4)  // 92160 B
#define NT (K_DIM / BK)                  // 196

__device__ __forceinline__ void cp_async16(void* s, const void* g) {
    uint32_t sa = (uint32_t)__cvta_generic_to_shared(s);
    asm volatile("cp.async.cg.shared.global [%0], [%1], 16;\n" :: "r"(sa), "l"(g));
}
__device__ __forceinline__ uint32_t f2tf32(float f) {
    uint32_t u;
    asm("cvt.rna.tf32.f32 %0, %1;" : "=r"(u) : "f"(f));
    return u;
}

__global__ __launch_bounds__(256, 1)
void gemm_fused(const float* __restrict__ A, const float* __restrict__ B,
                const float* __restrict__ Wd, float* __restrict__ out) {
    extern __shared__ float sm[];

    const int tid  = threadIdx.x;
    const int warp = tid >> 5;
    const int lane = tid & 31;
    const int wm   = warp & 1;      // 2 warps along M (64 rows each)
    const int wn   = warp >> 1;     // 4 warps along N (64 cols each)
    const int g    = lane >> 2;     // 0..7
    const int t4   = lane & 3;      // 0..3

    const int gx = blockIdx.x;      // N tile 0..3
    const int gy = blockIdx.y;      // M tile 0..63
    const int b  = gy >> 1;
    const int c0 = (gy & 1) * BM;

    const float* Ab = A + (size_t)(gy * BM) * K_DIM;
    const float* Bb = B + (size_t)(gx * BN) * K_DIM;

    const int lr = tid >> 2;          // 0..63
    const int lc = (tid & 3) * 4;     // 0,4,8,12

    float acc[4][8][4];
    #pragma unroll
    for (int i = 0; i < 4; i++)
        #pragma unroll
        for (int j = 0; j < 8; j++)
            #pragma unroll
            for (int k = 0; k < 4; k++) acc[i][j][k] = 0.f;

    auto load_stage = [&](int s, int kt) {
        float* st = sm + s * ST_FL;
        #pragma unroll
        for (int i = 0; i < 6; i++) {
            int r = lr + i * 64;
            if (r < BM) {
                cp_async16(st + r * LDSS + lc,
                           Ab + (size_t)r * K_DIM + kt * BK + lc);
            } else {
                int rb = r - BM;
                cp_async16(st + A_ST_FL + rb * LDSS + lc,
                           Bb + (size_t)rb * K_DIM + kt * BK + lc);
            }
        }
    };

    load_stage(0, 0);
    asm volatile("cp.async.commit_group;\n" ::: "memory");
    load_stage(1, 1);
    asm volatile("cp.async.commit_group;\n" ::: "memory");

    #pragma unroll 1
    for (int kt = 0; kt < NT; ++kt) {
        asm volatile("cp.async.wait_group 1;\n" ::: "memory");
        __syncthreads();

        if (kt + 2 < NT) {
            int s2 = kt + 2;
            s2 -= (s2 >= STAGES) ? STAGES : 0;
            s2 -= (s2 >= STAGES) ? STAGES : 0;   // (kt+2) % 3 cheap
            load_stage((kt + 2) % STAGES, kt + 2);
        }
        asm volatile("cp.async.commit_group;\n" ::: "memory");

        const float* As = sm + (kt % STAGES) * ST_FL;
        const float* Bs = As + A_ST_FL;

        #pragma unroll
        for (int kk = 0; kk < BK; kk += 8) {
            uint32_t af[4][4];
            #pragma unroll
            for (int mi = 0; mi < 4; mi++) {
                const float* ar = As + (wm * 64 + mi * 16 + g) * LDSS + kk + t4;
                af[mi][0] = f2tf32(ar[0]);
                af[mi][1] = f2tf32(ar[8 * LDSS]);
                af[mi][2] = f2tf32(ar[4]);
                af[mi][3] = f2tf32(ar[8 * LDSS + 4]);
            }
            uint32_t bf[8][2];
            #pragma unroll
            for (int ni = 0; ni < 8; ni++) {
                const float* br = Bs + (wn * 64 + ni * 8 + g) * LDSS + kk + t4;
                bf[ni][0] = f2tf32(br[0]);
                bf[ni][1] = f2tf32(br[4]);
            }
            #pragma unroll
            for (int mi = 0; mi < 4; mi++)
                #pragma unroll
                for (int ni = 0; ni < 8; ni++) {
                    asm volatile(
                        "mma.sync.aligned.m16n8k8.row.col.f32.tf32.tf32.f32 "
                        "{%0,%1,%2,%3}, {%4,%5,%6,%7}, {%8,%9}, {%0,%1,%2,%3};\n"
                        : "+f"(acc[mi][ni][0]), "+f"(acc[mi][ni][1]),
                          "+f"(acc[mi][ni][2]), "+f"(acc[mi][ni][3])
                        : "r"(af[mi][0]), "r"(af[mi][1]), "r"(af[mi][2]), "r"(af[mi][3]),
                          "r"(bf[ni][0]), "r"(bf[ni][1]));
                }
        }
        __syncthreads();
    }

    // ---------------- fused epilogue ----------------
    // Thread owns rows wm*64+mi*16+g(+8), cols wn*64+ni*8+t4*2+p.
    // out[b, n] += sum_rows acc * Wd[n, c0+row]
    #pragma unroll
    for (int ni = 0; ni < 8; ni++) {
        #pragma unroll
        for (int p = 0; p < 2; p++) {
            const int n = gx * BN + wn * 64 + ni * 8 + t4 * 2 + p;
            const float* wdp = Wd + (size_t)n * 256 + c0 + wm * 64 + g;
            float s = 0.f;
            #pragma unroll
            for (int mi = 0; mi < 4; mi++) {
                s += acc[mi][ni][p]     * __ldg(wdp + mi * 16);
                s += acc[mi][ni][2 + p] * __ldg(wdp + mi * 16 + 8);
            }
            // reduce over g (lane bits 2..4)
            s += __shfl_xor_sync(0xffffffffu, s, 16);
            s += __shfl_xor_sync(0xffffffffu, s, 8);
            s += __shfl_xor_sync(0xffffffffu, s, 4);
            if (g == 0)
                atomicAdd(&out[(size_t)b * N_DIM + n], s);
        }
    }
}

__global__ __launch_bounds__(1024)
void init_out(const float* __restrict__ Wb, float* __restrict__ out) {
    int i = blockIdx.x * 1024 + threadIdx.x;
    out[i] = Wb[i & (N_DIM - 1)];
}

extern "C" void kernel_launch(void* const* d_in, const int* in_sizes, int n_in,
                              void* d_out, int out_size) {
    const float* x  = (const float*)d_in[0];  // (32,256,56,56) = [8192 x 3136]
    const float* Ws = (const float*)d_in[1];  // (1024,56,56)   = [1024 x 3136]
    const float* Wd = (const float*)d_in[2];  // (1024,256)
    const float* Wb = (const float*)d_in[3];  // (1024)
    float* out = (float*)d_out;               // (32,1024) fp32

    static bool attr_set = false;
    if (!attr_set) {
        cudaFuncSetAttribute(gemm_fused,
                             cudaFuncAttributeMaxDynamicSharedMemorySize, SMEM_BYTES);
        attr_set = true;
    }

    init_out<<<32, 1024>>>(Wb, out);
    dim3 grid(N_DIM / BN, M_DIM / BM);   // (4, 64)
    gemm_fused<<<grid, 256, SMEM_BYTES>>>(x, Ws, Wd, out);
}

// round 6
// speedup vs baseline: 1.2385x; 1.0328x over previous
#include <cuda_runtime.h>
#include <cstdint>

// out[b,n] = sum_{c,hw} x[b,c,hw] * W_s[n,hw] * W_d[n,c] + W_b[n]
// Fused: tf32 mma.sync GEMM D[(b,c),n] = x . Ws^T, epilogue contracts c with W_d
// directly from accumulators (out pre-initialized to W_b).

#define M_DIM 8192
#define N_DIM 1024
#define K_DIM 3136
#define BM 128
#define BN 256
#define BK 16
#define STAGES 3
#define LDSS 20                          // padded row stride (floats)
#define A_ST_FL (BM * LDSS)              // 2560 floats
#define B_ST_FL (BN * LDSS)              // 5120 floats
#define ST_FL   (A_ST_FL + B_ST_FL)      // 7680 floats = 30720 B
#define SMEM_BYTES (STAGES * ST_FL * 4)  // 92160 B
#define NT (K_DIM / BK)                  // 196

__device__ __forceinline__ void cp_async16(void* s, const void* g) {
    uint32_t sa = (uint32_t)__cvta_generic_to_shared(s);
    asm volatile("cp.async.cg.shared.global [%0], [%1], 16;\n" :: "r"(sa), "l"(g));
}

__global__ __launch_bounds__(512, 1)
void gemm_fused(const float* __restrict__ A, const float* __restrict__ B,
                const float* __restrict__ Wd, float* __restrict__ out) {
    extern __shared__ float sm[];

    const int tid  = threadIdx.x;
    const int warp = tid >> 5;      // 0..15
    const int lane = tid & 31;
    const int wm   = warp & 3;      // 4 warps along M (32 rows each)
    const int wn   = warp >> 2;     // 4 warps along N (64 cols each)
    const int g    = lane >> 2;     // 0..7
    const int t4   = lane & 3;      // 0..3

    const int gx = blockIdx.x;      // N tile 0..3
    const int gy = blockIdx.y;      // M tile 0..63
    const int b  = gy >> 1;
    const int c0 = (gy & 1) * BM;

    const float* Ab = A + (size_t)(gy * BM) * K_DIM;
    const float* Bb = B + (size_t)(gx * BN) * K_DIM;

    const int lr = tid >> 2;          // 0..127
    const int lc = (tid & 3) * 4;     // 0,4,8,12

    float acc[2][8][4];
    #pragma unroll
    for (int i = 0; i < 2; i++)
        #pragma unroll
        for (int j = 0; j < 8; j++)
            #pragma unroll
            for (int k = 0; k < 4; k++) acc[i][j][k] = 0.f;

    auto load_stage = [&](int s, int kt) {
        float* st = sm + s * ST_FL;
        // A: 128 rows, one 16B chunk per thread
        cp_async16(st + lr * LDSS + lc, Ab + (size_t)lr * K_DIM + kt * BK + lc);
        // B: 256 rows, two chunks per thread
        cp_async16(st + A_ST_FL + lr * LDSS + lc,
                   Bb + (size_t)lr * K_DIM + kt * BK + lc);
        cp_async16(st + A_ST_FL + (lr + 128) * LDSS + lc,
                   Bb + (size_t)(lr + 128) * K_DIM + kt * BK + lc);
    };

    load_stage(0, 0);
    asm volatile("cp.async.commit_group;\n" ::: "memory");
    load_stage(1, 1);
    asm volatile("cp.async.commit_group;\n" ::: "memory");

    int s_cur = 0, s_nxt = 2;
    #pragma unroll 1
    for (int kt = 0; kt < NT; ++kt) {
        asm volatile("cp.async.wait_group 1;\n" ::: "memory");
        __syncthreads();

        if (kt + 2 < NT) load_stage(s_nxt, kt + 2);
        asm volatile("cp.async.commit_group;\n" ::: "memory");

        const uint32_t* As = (const uint32_t*)(sm + s_cur * ST_FL);
        const uint32_t* Bs = As + A_ST_FL;

        #pragma unroll
        for (int kk = 0; kk < BK; kk += 8) {
            uint32_t af[2][4];
            #pragma unroll
            for (int mi = 0; mi < 2; mi++) {
                const uint32_t* ar = As + (wm * 32 + mi * 16 + g) * LDSS + kk + t4;
                af[mi][0] = ar[0];
                af[mi][1] = ar[8 * LDSS];
                af[mi][2] = ar[4];
                af[mi][3] = ar[8 * LDSS + 4];
            }
            uint32_t bf[8][2];
            #pragma unroll
            for (int ni = 0; ni < 8; ni++) {
                const uint32_t* br = Bs + (wn * 64 + ni * 8 + g) * LDSS + kk + t4;
                bf[ni][0] = br[0];
                bf[ni][1] = br[4];
            }
            #pragma unroll
            for (int mi = 0; mi < 2; mi++)
                #pragma unroll
                for (int ni = 0; ni < 8; ni++) {
                    asm volatile(
                        "mma.sync.aligned.m16n8k8.row.col.f32.tf32.tf32.f32 "
                        "{%0,%1,%2,%3}, {%4,%5,%6,%7}, {%8,%9}, {%0,%1,%2,%3};\n"
                        : "+f"(acc[mi][ni][0]), "+f"(acc[mi][ni][1]),
                          "+f"(acc[mi][ni][2]), "+f"(acc[mi][ni][3])
                        : "r"(af[mi][0]), "r"(af[mi][1]), "r"(af[mi][2]), "r"(af[mi][3]),
                          "r"(bf[ni][0]), "r"(bf[ni][1]));
                }
        }
        __syncthreads();

        s_cur = (s_cur == STAGES - 1) ? 0 : s_cur + 1;
        s_nxt = (s_nxt == STAGES - 1) ? 0 : s_nxt + 1;
    }

    // ---------------- fused epilogue ----------------
    // Thread owns rows wm*32+mi*16+g(+8), cols wn*64+ni*8+t4*2+p.
    // out[b,n] += sum_rows acc * Wd[n, c0+row]
    #pragma unroll
    for (int ni = 0; ni < 8; ni++) {
        #pragma unroll
        for (int p = 0; p < 2; p++) {
            const int n = gx * BN + wn * 64 + ni * 8 + t4 * 2 + p;
            const float* wdp = Wd + (size_t)n * 256 + c0 + wm * 32 + g;
            float s = 0.f;
            #pragma unroll
            for (int mi = 0; mi < 2; mi++) {
                s += acc[mi][ni][p]     * __ldg(wdp + mi * 16);
                s += acc[mi][ni][2 + p] * __ldg(wdp + mi * 16 + 8);
            }
            // reduce over g (lane bits 2..4)
            s += __shfl_xor_sync(0xffffffffu, s, 16);
            s += __shfl_xor_sync(0xffffffffu, s, 8);
            s += __shfl_xor_sync(0xffffffffu, s, 4);
            if (g == 0)
                atomicAdd(&out[(size_t)b * N_DIM + n], s);
        }
    }
}

__global__ __launch_bounds__(1024)
void init_out(const float* __restrict__ Wb, float* __restrict__ out) {
    int i = blockIdx.x * 1024 + threadIdx.x;
    out[i] = Wb[i & (N_DIM - 1)];
}

extern "C" void kernel_launch(void* const* d_in, const int* in_sizes, int n_in,
                              void* d_out, int out_size) {
    const float* x  = (const float*)d_in[0];  // (32,256,56,56) = [8192 x 3136]
    const float* Ws = (const float*)d_in[1];  // (1024,56,56)   = [1024 x 3136]
    const float* Wd = (const float*)d_in[2];  // (1024,256)
    const float* Wb = (const float*)d_in[3];  // (1024)
    float* out = (float*)d_out;               // (32,1024) fp32

    static bool attr_set = false;
    if (!attr_set) {
        cudaFuncSetAttribute(gemm_fused,
                             cudaFuncAttributeMaxDynamicSharedMemorySize, SMEM_BYTES);
        attr_set = true;
    }

    init_out<<<32, 1024>>>(Wb, out);
    dim3 grid(N_DIM / BN, M_DIM / BM);   // (4, 64)
    gemm_fused<<<grid, 512, SMEM_BYTES>>>(x, Ws, Wd, out);
}

// round 7
// speedup vs baseline: 1.3081x; 1.0562x over previous
#include <cuda_runtime.h>
#include <cstdint>

// out[b,n] = sum_{c,hw} x[b,c,hw] * W_s[n,hw] * W_d[n,c] + W_b[n]
// GEMM D[(b,c),n] = x . Ws^T (tf32 mma.sync), fused Wd epilogue via atomics.
// Ws preprocessed (RNA-rounded tf32, pair-interleaved) so B frags = LDS.64.
// x loaded pair-interleaved into smem via 4B cp.async so A frags = LDS.128.
// Split-K x4 for wave balance.

#define M_DIM 8192
#define N_DIM 1024
#define K_DIM 3136
#define BM 128
#define BN 256
#define STAGES 3
#define NTL 49                    // kt steps per split (196/4)
#define A_ST_FL 2048              // 128 rows x 16 k (floats)
#define B_ST_FL 4096              // 256 rows x 16 k
#define ST_FL   (A_ST_FL + B_ST_FL)          // 6144 floats = 24 KB
#define SMEM_BYTES (STAGES * ST_FL * 4)      // 73728 B

// B' layout: [ng 0..127][k8 0..391][slot i 0..31][u 0..1]
// slot i = g*4 + t  (g = n&7, t = k&3, u = (k>>2)&1), value Ws[ng*8+g][k8*8+t+4u]
__device__ float g_Bp[(size_t)128 * 392 * 64];

__device__ __forceinline__ void cp_async16(void* s, const void* g) {
    uint32_t sa = (uint32_t)__cvta_generic_to_shared(s);
    asm volatile("cp.async.cg.shared.global [%0], [%1], 16;\n" :: "r"(sa), "l"(g));
}
__device__ __forceinline__ void cp_async4(void* s, const void* g) {
    uint32_t sa = (uint32_t)__cvta_generic_to_shared(s);
    asm volatile("cp.async.ca.shared.global [%0], [%1], 4;\n" :: "r"(sa), "l"(g));
}
__device__ __forceinline__ uint32_t f2tf32(float f) {
    uint32_t u;
    asm("cvt.rna.tf32.f32 %0, %1;" : "=r"(u) : "f"(f));
    return u;
}

// ---------------- Ws preprocess: RNA-round + pair-interleave ----------------
__global__ __launch_bounds__(256)
void prep_B(const float* __restrict__ Ws) {
    const int ng  = blockIdx.y;                       // 0..127
    const int idx = blockIdx.x * 256 + threadIdx.x;   // 0..12543
    const int k8  = idx >> 5;                         // 0..391
    const int i   = idx & 31;
    const int g = i >> 2, t = i & 3;
    const float* src = Ws + (size_t)(ng * 8 + g) * K_DIM + k8 * 8 + t;
    float2 v;
    v.x = __uint_as_float(f2tf32(src[0]));
    v.y = __uint_as_float(f2tf32(src[4]));
    *reinterpret_cast<float2*>(g_Bp + ((size_t)(ng * 392 + k8) * 32 + i) * 2) = v;
}

__global__ __launch_bounds__(1024)
void init_out(const float* __restrict__ Wb, float* __restrict__ out) {
    int i = blockIdx.x * 1024 + threadIdx.x;
    out[i] = Wb[i & (N_DIM - 1)];
}

// ---------------- fused GEMM ----------------
__global__ __launch_bounds__(512, 1)
void gemm_fused(const float* __restrict__ A,
                const float* __restrict__ Wd, float* __restrict__ out) {
    extern __shared__ float sm[];

    const int tid  = threadIdx.x;
    const int warp = tid >> 5;      // 0..15
    const int lane = tid & 31;
    const int wm   = warp & 3;      // 4 warps along M (32 rows)
    const int wn   = warp >> 2;     // 4 warps along N (64 cols)
    const int g    = lane >> 2;
    const int t4   = lane & 3;

    const int gx = blockIdx.x;      // 0..3   N tile
    const int gy = blockIdx.y;      // 0..63  M tile
    const int sp = blockIdx.z;      // 0..3   K split
    const int b  = gy >> 1;
    const int c0 = (gy & 1) * BM;

    // ---- per-thread load pointers ----
    // A: slot s = tid: rg=s>>6, kb=(s>>5)&1, i=s&31, g=i>>2, t=i&3
    const int arg = tid >> 6, akb = (tid >> 5) & 1, ai = tid & 31;
    const int ag = ai >> 2, at = ai & 3;
    const float* apt = A + (size_t)(gy * BM + arg * 16 + ag) * K_DIM
                         + sp * (NTL * 16) + akb * 8 + at;
    float* adst = sm /*stage base added later*/ + tid * 4;  // 16B per thread

    // B: chunks c = tid and tid+512: ng=c>>5, j=c&31
    const float* bpt0 = g_Bp + ((size_t)(gx * 32 + (tid >> 5)) * 392 + sp * (NTL * 2)) * 64
                             + (tid & 31) * 4;
    const float* bpt1 = bpt0 + (size_t)16 * 392 * 64;   // ng + 16
    float* bdst0 = sm + A_ST_FL + tid * 4;
    float* bdst1 = sm + A_ST_FL + 2048 + tid * 4;

    float acc[2][8][4];
    #pragma unroll
    for (int i = 0; i < 2; i++)
        #pragma unroll
        for (int j = 0; j < 8; j++)
            #pragma unroll
            for (int k = 0; k < 4; k++) acc[i][j][k] = 0.f;

    auto load_stage = [&](int s, const float* ap, const float* bp0, const float* bp1) {
        float* st = sm + s * ST_FL;
        float* ad = st + tid * 4;
        cp_async4(ad + 0, ap);
        cp_async4(ad + 1, ap + 8 * K_DIM);
        cp_async4(ad + 2, ap + 4);
        cp_async4(ad + 3, ap + 8 * K_DIM + 4);
        cp_async16(st + A_ST_FL + tid * 4, bp0);
        cp_async16(st + A_ST_FL + 2048 + tid * 4, bp1);
    };

    // prologue: stages 0,1
    load_stage(0, apt, bpt0, bpt1);
    asm volatile("cp.async.commit_group;\n" ::: "memory");
    load_stage(1, apt + 16, bpt0 + 128, bpt1 + 128);
    asm volatile("cp.async.commit_group;\n" ::: "memory");
    apt += 32; bpt0 += 256; bpt1 += 256;    // positioned at kt+2

    int s_cur = 0, s_load = 2;
    #pragma unroll 1
    for (int kt = 0; kt < NTL; ++kt) {
        asm volatile("cp.async.wait_group 1;\n" ::: "memory");
        __syncthreads();

        if (kt + 2 < NTL) {
            load_stage(s_load, apt, bpt0, bpt1);
            apt += 16; bpt0 += 128; bpt1 += 128;
        }
        asm volatile("cp.async.commit_group;\n" ::: "memory");

        const float* As = sm + s_cur * ST_FL;
        const float* Bs = As + A_ST_FL;

        #pragma unroll
        for (int kk2 = 0; kk2 < 2; ++kk2) {
            // A frags: one LDS.128 per mi, then RNA-round
            uint32_t af[2][4];
            #pragma unroll
            for (int mi = 0; mi < 2; mi++) {
                float4 v = *reinterpret_cast<const float4*>(
                    As + (wm * 2 + mi) * 256 + kk2 * 128 + lane * 4);
                af[mi][0] = f2tf32(v.x);
                af[mi][1] = f2tf32(v.y);
                af[mi][2] = f2tf32(v.z);
                af[mi][3] = f2tf32(v.w);
            }
            // B frags: one LDS.64 per ni (pre-rounded)
            uint32_t bf[8][2];
            #pragma unroll
            for (int ni = 0; ni < 8; ni++) {
                float2 v = *reinterpret_cast<const float2*>(
                    Bs + (wn * 8 + ni) * 128 + kk2 * 64 + lane * 2);
                bf[ni][0] = __float_as_uint(v.x);
                bf[ni][1] = __float_as_uint(v.y);
            }
            #pragma unroll
            for (int mi = 0; mi < 2; mi++)
                #pragma unroll
                for (int ni = 0; ni < 8; ni++) {
                    asm volatile(
                        "mma.sync.aligned.m16n8k8.row.col.f32.tf32.tf32.f32 "
                        "{%0,%1,%2,%3}, {%4,%5,%6,%7}, {%8,%9}, {%0,%1,%2,%3};\n"
                        : "+f"(acc[mi][ni][0]), "+f"(acc[mi][ni][1]),
                          "+f"(acc[mi][ni][2]), "+f"(acc[mi][ni][3])
                        : "r"(af[mi][0]), "r"(af[mi][1]), "r"(af[mi][2]), "r"(af[mi][3]),
                          "r"(bf[ni][0]), "r"(bf[ni][1]));
                }
        }

        s_cur  = (s_cur  == STAGES - 1) ? 0 : s_cur + 1;
        s_load = (s_load == STAGES - 1) ? 0 : s_load + 1;
    }

    // ---------------- fused epilogue ----------------
    // rows: c0 + wm*32 + mi*16 + g (+8); cols: gx*BN + wn*64 + ni*8 + t4*2 + p
    #pragma unroll
    for (int ni = 0; ni < 8; ni++) {
        #pragma unroll
        for (int p = 0; p < 2; p++) {
            const int n = gx * BN + wn * 64 + ni * 8 + t4 * 2 + p;
            const float* wdp = Wd + (size_t)n * 256 + c0 + wm * 32 + g;
            float s = 0.f;
            #pragma unroll
            for (int mi = 0; mi < 2; mi++) {
                s += acc[mi][ni][p]     * __ldg(wdp + mi * 16);
                s += acc[mi][ni][2 + p] * __ldg(wdp + mi * 16 + 8);
            }
            s += __shfl_xor_sync(0xffffffffu, s, 16);
            s += __shfl_xor_sync(0xffffffffu, s, 8);
            s += __shfl_xor_sync(0xffffffffu, s, 4);
            if (g == 0)
                atomicAdd(&out[(size_t)b * N_DIM + n], s);
        }
    }
}

extern "C" void kernel_launch(void* const* d_in, const int* in_sizes, int n_in,
                              void* d_out, int out_size) {
    const float* x  = (const float*)d_in[0];  // [8192 x 3136]
    const float* Ws = (const float*)d_in[1];  // [1024 x 3136]
    const float* Wd = (const float*)d_in[2];  // [1024 x 256]
    const float* Wb = (const float*)d_in[3];  // [1024]
    float* out = (float*)d_out;               // [32 x 1024] fp32

    static bool attr_set = false;
    if (!attr_set) {
        cudaFuncSetAttribute(gemm_fused,
                             cudaFuncAttributeMaxDynamicSharedMemorySize, SMEM_BYTES);
        attr_set = true;
    }

    dim3 pgrid(49, 128);                       // 49*256 = 12544 threads per ng
    prep_B<<<pgrid, 256>>>(Ws);
    init_out<<<32, 1024>>>(Wb, out);
    dim3 grid(N_DIM / BN, M_DIM / BM, 4);      // (4, 64, 4) = 1024 CTAs
    gemm_fused<<<grid, 512, SMEM_BYTES>>>(x, Wd, out);
}

// round 8
// speedup vs baseline: 1.8484x; 1.4131x over previous
#include <cuda_runtime.h>
#include <cuda_fp16.h>
#include <cstdint>

// out[b,n] = sum_{c,hw} x[b,c,hw] * W_s[n,hw] * W_d[n,c] + W_b[n]
// GEMM D[(b,c),n] = x . Ws^T via fp16 mma.sync m16n8k16 (fp32 accum),
// Ws pre-converted to fp16; x converted in-register. Fused Wd epilogue.
// Split-K x4. out pre-initialized to W_b.

#define M_DIM 8192
#define N_DIM 1024
#define K_DIM 3136
#define BM 128
#define BN 256
#define STAGES 3
#define NTL 49                       // k16 steps per split (784/16)
#define A_ST_FL 2048                 // 128 rows x 16 fp32
#define B_ST_FL 2048                 // 256 rows x 16 fp16 (= 2048 floats)
#define ST_FL   (A_ST_FL + B_ST_FL)  // 4096 floats = 16 KB
#define SMEM_BYTES (STAGES * ST_FL * 4)   // 49152
#define KSPL 784                     // K per split

__device__ __align__(16) __half g_Bh[(size_t)N_DIM * K_DIM];  // 6.4 MB fp16 Ws

__device__ __forceinline__ void cp_async16(void* s, const void* g) {
    uint32_t sa = (uint32_t)__cvta_generic_to_shared(s);
    asm volatile("cp.async.cg.shared.global [%0], [%1], 16;\n" :: "r"(sa), "l"(g));
}
__device__ __forceinline__ uint32_t pack_h2(float lo, float hi) {
    __half2 h = __floats2half2_rn(lo, hi);
    return *reinterpret_cast<uint32_t*>(&h);
}

// ---------------- Ws -> fp16 ----------------
__global__ __launch_bounds__(256)
void prep_Bh(const float* __restrict__ Ws) {
    size_t i = (size_t)blockIdx.x * 256 + threadIdx.x;   // over 802816 float4s
    float4 v = reinterpret_cast<const float4*>(Ws)[i];
    uint2 o;
    o.x = pack_h2(v.x, v.y);
    o.y = pack_h2(v.z, v.w);
    reinterpret_cast<uint2*>(g_Bh)[i] = o;
}

__global__ __launch_bounds__(1024)
void init_out(const float* __restrict__ Wb, float* __restrict__ out) {
    int i = blockIdx.x * 1024 + threadIdx.x;
    out[i] = Wb[i & (N_DIM - 1)];
}

// ---------------- fused GEMM ----------------
__global__ __launch_bounds__(512, 1)
void gemm_fused(const float* __restrict__ A,
                const float* __restrict__ Wd, float* __restrict__ out) {
    extern __shared__ float sm[];

    const int tid  = threadIdx.x;
    const int warp = tid >> 5;      // 0..15
    const int lane = tid & 31;
    const int wm   = warp & 3;      // 4 warps along M (32 rows)
    const int wn   = warp >> 2;     // 4 warps along N (64 cols)
    const int g    = lane >> 2;
    const int t4   = lane & 3;

    const int gx = blockIdx.x;      // 0..3  N tile
    const int gy = blockIdx.y;      // 0..63 M tile
    const int sp = blockIdx.z;      // 0..3  K split
    const int b  = gy >> 1;
    const int c0 = (gy & 1) * BM;

    // cp.async source pointers
    const int arow = tid >> 2, achk = (tid & 3) * 4;       // A: 128 rows x 4 chunks
    const int brow = tid >> 1, bhlf = (tid & 1) * 8;       // B: 256 rows x 2 chunks
    const float*  apt = A + (size_t)(gy * BM + arow) * K_DIM + sp * KSPL + achk;
    const __half* bpt = g_Bh + (size_t)(gx * BN + brow) * K_DIM + sp * KSPL + bhlf;

    // ldmatrix per-lane address offset within B stage (in halfs)
    const int lm_row  = ((lane >> 4) & 1) * 8 + (lane & 7);
    const int lm_half = ((lane >> 3) & 1) * 8;

    float acc[2][8][4];
    #pragma unroll
    for (int i = 0; i < 2; i++)
        #pragma unroll
        for (int j = 0; j < 8; j++)
            #pragma unroll
            for (int k = 0; k < 4; k++) acc[i][j][k] = 0.f;

    auto load_stage = [&](int s, int kt) {
        float* st = sm + s * ST_FL;
        cp_async16(st + arow * 16 + achk, apt + kt * 16);
        cp_async16((__half*)(st + A_ST_FL) + brow * 16 + bhlf, bpt + kt * 16);
    };

    load_stage(0, 0);
    asm volatile("cp.async.commit_group;\n" ::: "memory");
    load_stage(1, 1);
    asm volatile("cp.async.commit_group;\n" ::: "memory");

    int s_cur = 0, s_load = 2;
    #pragma unroll 1
    for (int kt = 0; kt < NTL; ++kt) {
        asm volatile("cp.async.wait_group 1;\n" ::: "memory");
        __syncthreads();

        if (kt + 2 < NTL) load_stage(s_load, kt + 2);
        asm volatile("cp.async.commit_group;\n" ::: "memory");

        const float* As = sm + s_cur * ST_FL;
        const uint32_t smB = (uint32_t)__cvta_generic_to_shared(As + A_ST_FL);

        // A fragments: LDS.64 fp32 pairs -> fp16x2
        uint32_t af[2][4];
        #pragma unroll
        for (int mi = 0; mi < 2; mi++) {
            const int r0 = wm * 32 + mi * 16 + g;
            float2 v0 = *reinterpret_cast<const float2*>(As + r0 * 16 + 2 * t4);
            float2 v1 = *reinterpret_cast<const float2*>(As + (r0 + 8) * 16 + 2 * t4);
            float2 v2 = *reinterpret_cast<const float2*>(As + r0 * 16 + 2 * t4 + 8);
            float2 v3 = *reinterpret_cast<const float2*>(As + (r0 + 8) * 16 + 2 * t4 + 8);
            af[mi][0] = pack_h2(v0.x, v0.y);
            af[mi][1] = pack_h2(v1.x, v1.y);
            af[mi][2] = pack_h2(v2.x, v2.y);
            af[mi][3] = pack_h2(v3.x, v3.y);
        }
        // B fragments: ldmatrix x4 covers 2 n8-tiles
        uint32_t bf[8][2];
        #pragma unroll
        for (int np = 0; np < 4; np++) {
            uint32_t addr = smB + ((wn * 64 + np * 16 + lm_row) * 16 + lm_half) * 2;
            asm volatile(
                "ldmatrix.sync.aligned.m8n8.x4.shared.b16 {%0,%1,%2,%3}, [%4];\n"
                : "=r"(bf[2 * np][0]), "=r"(bf[2 * np][1]),
                  "=r"(bf[2 * np + 1][0]), "=r"(bf[2 * np + 1][1])
                : "r"(addr));
        }
        #pragma unroll
        for (int mi = 0; mi < 2; mi++)
            #pragma unroll
            for (int ni = 0; ni < 8; ni++) {
                asm volatile(
                    "mma.sync.aligned.m16n8k16.row.col.f32.f16.f16.f32 "
                    "{%0,%1,%2,%3}, {%4,%5,%6,%7}, {%8,%9}, {%0,%1,%2,%3};\n"
                    : "+f"(acc[mi][ni][0]), "+f"(acc[mi][ni][1]),
                      "+f"(acc[mi][ni][2]), "+f"(acc[mi][ni][3])
                    : "r"(af[mi][0]), "r"(af[mi][1]), "r"(af[mi][2]), "r"(af[mi][3]),
                      "r"(bf[ni][0]), "r"(bf[ni][1]));
            }

        s_cur  = (s_cur  == STAGES - 1) ? 0 : s_cur + 1;
        s_load = (s_load == STAGES - 1) ? 0 : s_load + 1;
    }

    // ---------------- fused epilogue ----------------
    // rows: c0 + wm*32 + mi*16 + g (+8); cols: gx*BN + wn*64 + ni*8 + 2*t4 + p
    #pragma unroll
    for (int ni = 0; ni < 8; ni++) {
        #pragma unroll
        for (int p = 0; p < 2; p++) {
            const int n = gx * BN + wn * 64 + ni * 8 + t4 * 2 + p;
            const float* wdp = Wd + (size_t)n * 256 + c0 + wm * 32 + g;
            float s = 0.f;
            #pragma unroll
            for (int mi = 0; mi < 2; mi++) {
                s += acc[mi][ni][p]     * __ldg(wdp + mi * 16);
                s += acc[mi][ni][2 + p] * __ldg(wdp + mi * 16 + 8);
            }
            s += __shfl_xor_sync(0xffffffffu, s, 16);
            s += __shfl_xor_sync(0xffffffffu, s, 8);
            s += __shfl_xor_sync(0xffffffffu, s, 4);
            if (g == 0)
                atomicAdd(&out[(size_t)b * N_DIM + n], s);
        }
    }
}

extern "C" void kernel_launch(void* const* d_in, const int* in_sizes, int n_in,
                              void* d_out, int out_size) {
    const float* x  = (const float*)d_in[0];  // [8192 x 3136]
    const float* Ws = (const float*)d_in[1];  // [1024 x 3136]
    const float* Wd = (const float*)d_in[2];  // [1024 x 256]
    const float* Wb = (const float*)d_in[3];  // [1024]
    float* out = (float*)d_out;               // [32 x 1024] fp32

    static bool attr_set = false;
    if (!attr_set) {
        cudaFuncSetAttribute(gemm_fused,
                             cudaFuncAttributeMaxDynamicSharedMemorySize, SMEM_BYTES);
        attr_set = true;
    }

    prep_Bh<<<3136, 256>>>(Ws);               // 802816 float4s
    init_out<<<32, 1024>>>(Wb, out);
    dim3 grid(N_DIM / BN, M_DIM / BM, 4);     // (4, 64, 4)
    gemm_fused<<<grid, 512, SMEM_BYTES>>>(x, Wd, out);
}

// round 9
// speedup vs baseline: 2.0305x; 1.0985x over previous
#include <cuda_runtime.h>
#include <cuda_fp16.h>
#include <cstdint>

// out[b,n] = sum_{c,hw} x[b,c,hw] * W_s[n,hw] * W_d[n,c] + W_b[n]
// GEMM D[(b,c),n] = x . Ws^T via fp16 mma.sync m16n8k16 (fp32 accum).
// Ws pre-converted to fp16. Fused Wd epilogue via atomics (out pre-set to W_b).
// BK=32 stages, padded smem (A rows 144B, B rows 80B) for conflict-free frag loads.
// Split-K {800,800,800,736} so every split is whole 32k stages.

#define M_DIM 8192
#define N_DIM 1024
#define K_DIM 3136
#define BM 128
#define BN 256
#define STAGES 3
#define A_ROW_B 144                    // 32 floats + 4 pad
#define B_ROW_B 80                     // 32 halfs + 8 pad
#define A_ST_BYTES (128 * A_ROW_B)     // 18432
#define B_ST_BYTES (256 * B_ROW_B)     // 20480
#define ST_BYTES   (A_ST_BYTES + B_ST_BYTES)   // 38912
#define SMEM_BYTES (STAGES * ST_BYTES)         // 116736

__device__ __align__(16) __half g_Bh[(size_t)N_DIM * K_DIM];  // 6.4 MB fp16 Ws

__device__ __forceinline__ void cp_async16(void* s, const void* g) {
    uint32_t sa = (uint32_t)__cvta_generic_to_shared(s);
    asm volatile("cp.async.cg.shared.global [%0], [%1], 16;\n" :: "r"(sa), "l"(g));
}
__device__ __forceinline__ uint32_t pack_h2(float lo, float hi) {
    __half2 h = __floats2half2_rn(lo, hi);
    return *reinterpret_cast<uint32_t*>(&h);
}

// ---------------- Ws -> fp16 ----------------
__global__ __launch_bounds__(256)
void prep_Bh(const float* __restrict__ Ws) {
    size_t i = (size_t)blockIdx.x * 256 + threadIdx.x;   // 802816 float4s
    float4 v = reinterpret_cast<const float4*>(Ws)[i];
    uint2 o;
    o.x = pack_h2(v.x, v.y);
    o.y = pack_h2(v.z, v.w);
    reinterpret_cast<uint2*>(g_Bh)[i] = o;
}

__global__ __launch_bounds__(1024)
void init_out(const float* __restrict__ Wb, float* __restrict__ out) {
    int i = blockIdx.x * 1024 + threadIdx.x;
    out[i] = Wb[i & (N_DIM - 1)];
}

// ---------------- fused GEMM ----------------
__global__ __launch_bounds__(512, 1)
void gemm_fused(const float* __restrict__ A,
                const float* __restrict__ Wd, float* __restrict__ out) {
    extern __shared__ char smem[];

    const int tid  = threadIdx.x;
    const int warp = tid >> 5;      // 0..15
    const int lane = tid & 31;
    const int wm   = warp & 3;      // 4 warps along M (32 rows)
    const int wn   = warp >> 2;     // 4 warps along N (64 cols)
    const int g    = lane >> 2;
    const int t4   = lane & 3;

    const int gx = blockIdx.x;      // 0..3  N tile
    const int gy = blockIdx.y;      // 0..63 M tile
    const int sp = blockIdx.z;      // 0..3  K split
    const int b  = gy >> 1;
    const int c0 = (gy & 1) * BM;

    const int kst = sp * 800;                 // split K start (floats)
    const int NT32 = (sp == 3) ? 23 : 25;     // 32k stages in this split

    // cp.async per-thread assignments (two 16B chunks each for A and B)
    const int ar0 = tid >> 3,           ac0 = (tid & 7) * 16;        // A chunk 0
    const int ar1 = (tid + 512) >> 3,   ac1 = ac0;                   // A chunk 1
    const int br0 = tid >> 2,           bc0 = (tid & 3) * 16;        // B chunk 0
    const int br1 = (tid + 512) >> 2,   bc1 = bc0;
    const float*  apt0 = A + (size_t)(gy * BM + ar0) * K_DIM + kst + (ac0 >> 2);
    const float*  apt1 = A + (size_t)(gy * BM + ar1) * K_DIM + kst + (ac1 >> 2);
    const __half* bpt0 = g_Bh + (size_t)(gx * BN + br0) * K_DIM + kst + (bc0 >> 1);
    const __half* bpt1 = g_Bh + (size_t)(gx * BN + br1) * K_DIM + kst + (bc1 >> 1);

    // ldmatrix lane mapping
    const int lm_row  = ((lane >> 4) & 1) * 8 + (lane & 7);
    const int lm_half = ((lane >> 3) & 1) * 8;

    float acc[2][8][4];
    #pragma unroll
    for (int i = 0; i < 2; i++)
        #pragma unroll
        for (int j = 0; j < 8; j++)
            #pragma unroll
            for (int k = 0; k < 4; k++) acc[i][j][k] = 0.f;

    auto load_stage = [&](int s, int kt) {
        char* st = smem + s * ST_BYTES;
        cp_async16(st + ar0 * A_ROW_B + ac0, apt0 + kt * 32);
        cp_async16(st + ar1 * A_ROW_B + ac1, apt1 + kt * 32);
        cp_async16(st + A_ST_BYTES + br0 * B_ROW_B + bc0, bpt0 + kt * 32);
        cp_async16(st + A_ST_BYTES + br1 * B_ROW_B + bc1, bpt1 + kt * 32);
    };

    load_stage(0, 0);
    asm volatile("cp.async.commit_group;\n" ::: "memory");
    load_stage(1, 1);
    asm volatile("cp.async.commit_group;\n" ::: "memory");

    // per-warp fragment base offsets
    const int aoff = (wm * 32 + g) * A_ROW_B + t4 * 8;   // bytes (2 floats per t4 step)

    int s_cur = 0, s_load = 2;
    #pragma unroll 1
    for (int kt = 0; kt < NT32; ++kt) {
        asm volatile("cp.async.wait_group 1;\n" ::: "memory");
        __syncthreads();

        if (kt + 2 < NT32) load_stage(s_load, kt + 2);
        asm volatile("cp.async.commit_group;\n" ::: "memory");

        const char* st = smem + s_cur * ST_BYTES;
        const char* Asb = st + aoff;
        const uint32_t smB = (uint32_t)__cvta_generic_to_shared(st + A_ST_BYTES);

        uint32_t af0[2][4], af1[2][4], bf0[8][2], bf1[8][2];

        // -------- half 0 fragments --------
        #pragma unroll
        for (int mi = 0; mi < 2; mi++) {
            const char* p = Asb + mi * 16 * A_ROW_B;
            float2 v0 = *(const float2*)(p);
            float2 v1 = *(const float2*)(p + 8 * A_ROW_B);
            float2 v2 = *(const float2*)(p + 32);
            float2 v3 = *(const float2*)(p + 8 * A_ROW_B + 32);
            af0[mi][0] = pack_h2(v0.x, v0.y);
            af0[mi][1] = pack_h2(v1.x, v1.y);
            af0[mi][2] = pack_h2(v2.x, v2.y);
            af0[mi][3] = pack_h2(v3.x, v3.y);
        }
        #pragma unroll
        for (int np = 0; np < 4; np++) {
            uint32_t addr = smB + ((wn * 64 + np * 16 + lm_row) * B_ROW_B) + (lm_half * 2);
            asm volatile(
                "ldmatrix.sync.aligned.m8n8.x4.shared.b16 {%0,%1,%2,%3}, [%4];\n"
                : "=r"(bf0[2 * np][0]), "=r"(bf0[2 * np][1]),
                  "=r"(bf0[2 * np + 1][0]), "=r"(bf0[2 * np + 1][1])
                : "r"(addr));
        }
        // -------- half 1 fragments --------
        #pragma unroll
        for (int mi = 0; mi < 2; mi++) {
            const char* p = Asb + mi * 16 * A_ROW_B + 64;
            float2 v0 = *(const float2*)(p);
            float2 v1 = *(const float2*)(p + 8 * A_ROW_B);
            float2 v2 = *(const float2*)(p + 32);
            float2 v3 = *(const float2*)(p + 8 * A_ROW_B + 32);
            af1[mi][0] = pack_h2(v0.x, v0.y);
            af1[mi][1] = pack_h2(v1.x, v1.y);
            af1[mi][2] = pack_h2(v2.x, v2.y);
            af1[mi][3] = pack_h2(v3.x, v3.y);
        }
        #pragma unroll
        for (int np = 0; np < 4; np++) {
            uint32_t addr = smB + ((wn * 64 + np * 16 + lm_row) * B_ROW_B) + ((16 + lm_half) * 2);
            asm volatile(
                "ldmatrix.sync.aligned.m8n8.x4.shared.b16 {%0,%1,%2,%3}, [%4];\n"
                : "=r"(bf1[2 * np][0]), "=r"(bf1[2 * np][1]),
                  "=r"(bf1[2 * np + 1][0]), "=r"(bf1[2 * np + 1][1])
                : "r"(addr));
        }
        // -------- MMAs --------
        #pragma unroll
        for (int mi = 0; mi < 2; mi++)
            #pragma unroll
            for (int ni = 0; ni < 8; ni++) {
                asm volatile(
                    "mma.sync.aligned.m16n8k16.row.col.f32.f16.f16.f32 "
                    "{%0,%1,%2,%3}, {%4,%5,%6,%7}, {%8,%9}, {%0,%1,%2,%3};\n"
                    : "+f"(acc[mi][ni][0]), "+f"(acc[mi][ni][1]),
                      "+f"(acc[mi][ni][2]), "+f"(acc[mi][ni][3])
                    : "r"(af0[mi][0]), "r"(af0[mi][1]), "r"(af0[mi][2]), "r"(af0[mi][3]),
                      "r"(bf0[ni][0]), "r"(bf0[ni][1]));
            }
        #pragma unroll
        for (int mi = 0; mi < 2; mi++)
            #pragma unroll
            for (int ni = 0; ni < 8; ni++) {
                asm volatile(
                    "mma.sync.aligned.m16n8k16.row.col.f32.f16.f16.f32 "
                    "{%0,%1,%2,%3}, {%4,%5,%6,%7}, {%8,%9}, {%0,%1,%2,%3};\n"
                    : "+f"(acc[mi][ni][0]), "+f"(acc[mi][ni][1]),
                      "+f"(acc[mi][ni][2]), "+f"(acc[mi][ni][3])
                    : "r"(af1[mi][0]), "r"(af1[mi][1]), "r"(af1[mi][2]), "r"(af1[mi][3]),
                      "r"(bf1[ni][0]), "r"(bf1[ni][1]));
            }

        s_cur  = (s_cur  == STAGES - 1) ? 0 : s_cur + 1;
        s_load = (s_load == STAGES - 1) ? 0 : s_load + 1;
    }

    // ---------------- fused epilogue ----------------
    // rows: c0 + wm*32 + mi*16 + g (+8); cols: gx*BN + wn*64 + ni*8 + 2*t4 + p
    #pragma unroll
    for (int ni = 0; ni < 8; ni++) {
        #pragma unroll
        for (int p = 0; p < 2; p++) {
            const int n = gx * BN + wn * 64 + ni * 8 + t4 * 2 + p;
            const float* wdp = Wd + (size_t)n * 256 + c0 + wm * 32 + g;
            float s = 0.f;
            #pragma unroll
            for (int mi = 0; mi < 2; mi++) {
                s += acc[mi][ni][p]     * __ldg(wdp + mi * 16);
                s += acc[mi][ni][2 + p] * __ldg(wdp + mi * 16 + 8);
            }
            s += __shfl_xor_sync(0xffffffffu, s, 16);
            s += __shfl_xor_sync(0xffffffffu, s, 8);
            s += __shfl_xor_sync(0xffffffffu, s, 4);
            if (g == 0)
                atomicAdd(&out[(size_t)b * N_DIM + n], s);
        }
    }
}

extern "C" void kernel_launch(void* const* d_in, const int* in_sizes, int n_in,
                              void* d_out, int out_size) {
    const float* x  = (const float*)d_in[0];  // [8192 x 3136]
    const float* Ws = (const float*)d_in[1];  // [1024 x 3136]
    const float* Wd = (const float*)d_in[2];  // [1024 x 256]
    const float* Wb = (const float*)d_in[3];  // [1024]
    float* out = (float*)d_out;               // [32 x 1024] fp32

    static bool attr_set = false;
    if (!attr_set) {
        cudaFuncSetAttribute(gemm_fused,
                             cudaFuncAttributeMaxDynamicSharedMemorySize, SMEM_BYTES);
        attr_set = true;
    }

    prep_Bh<<<3136, 256>>>(Ws);               // 802816 float4s
    init_out<<<32, 1024>>>(Wb, out);
    dim3 grid(N_DIM / BN, M_DIM / BM, 4);     // (4, 64, 4)
    gemm_fused<<<grid, 512, SMEM_BYTES>>>(x, Wd, out);
}

// round 10
// speedup vs baseline: 2.2141x; 1.0904x over previous
#include <cuda_runtime.h>
#include <cuda_fp16.h>
#include <cstdint>

// out[b,n] = sum_{c,hw} x[b,c,hw] * W_s[n,hw] * W_d[n,c] + W_b[n]
// GEMM D[(b,c),n] = x . Ws^T via fp16 mma.sync m16n8k16 (fp32 accum).
// Ws pre-converted fp16. Fused Wd epilogue via atomics (out pre-set to W_b).
// BM=BN=128, 256 thr, 2 CTAs/SM (barrier overlap). BK=32, padded smem.
// Split-K {800,800,800,736}.

#define M_DIM 8192
#define N_DIM 1024
#define K_DIM 3136
#define BM 128
#define BN 128
#define STAGES 3
#define A_ROW_B 144                    // 32 floats + 16B pad
#define B_ROW_B 80                     // 32 halfs + 16B pad
#define A_ST_BYTES (128 * A_ROW_B)     // 18432
#define B_ST_BYTES (128 * B_ROW_B)     // 10240
#define ST_BYTES   (A_ST_BYTES + B_ST_BYTES)   // 28672
#define SMEM_BYTES (STAGES * ST_BYTES)         // 86016

__device__ __align__(16) __half g_Bh[(size_t)N_DIM * K_DIM];  // 6.4 MB fp16 Ws

__device__ __forceinline__ void cp_async16(void* s, const void* g) {
    uint32_t sa = (uint32_t)__cvta_generic_to_shared(s);
    asm volatile("cp.async.cg.shared.global [%0], [%1], 16;\n" :: "r"(sa), "l"(g));
}
__device__ __forceinline__ uint32_t pack_h2(float lo, float hi) {
    __half2 h = __floats2half2_rn(lo, hi);
    return *reinterpret_cast<uint32_t*>(&h);
}

// ---------------- Ws -> fp16 ----------------
__global__ __launch_bounds__(256)
void prep_Bh(const float* __restrict__ Ws) {
    size_t i = (size_t)blockIdx.x * 256 + threadIdx.x;   // 802816 float4s
    float4 v = reinterpret_cast<const float4*>(Ws)[i];
    uint2 o;
    o.x = pack_h2(v.x, v.y);
    o.y = pack_h2(v.z, v.w);
    reinterpret_cast<uint2*>(g_Bh)[i] = o;
}

__global__ __launch_bounds__(1024)
void init_out(const float* __restrict__ Wb, float* __restrict__ out) {
    int i = blockIdx.x * 1024 + threadIdx.x;
    out[i] = Wb[i & (N_DIM - 1)];
}

// ---------------- fused GEMM ----------------
__global__ __launch_bounds__(256, 2)
void gemm_fused(const float* __restrict__ A,
                const float* __restrict__ Wd, float* __restrict__ out) {
    extern __shared__ char smem[];

    const int tid  = threadIdx.x;
    const int warp = tid >> 5;      // 0..7
    const int lane = tid & 31;
    const int wm   = warp & 3;      // 4 warps along M (32 rows)
    const int wn   = warp >> 2;     // 2 warps along N (64 cols)
    const int g    = lane >> 2;
    const int t4   = lane & 3;

    const int gx = blockIdx.x;      // 0..7  N tile
    const int gy = blockIdx.y;      // 0..63 M tile
    const int sp = blockIdx.z;      // 0..3  K split
    const int b  = gy >> 1;
    const int c0 = (gy & 1) * BM;

    const int kst  = sp * 800;
    const int NT32 = (sp == 3) ? 23 : 25;

    // cp.async assignments: A 1024 chunks (4/thread), B 512 chunks (2/thread)
    const int arow = tid >> 3, acol = (tid & 7) * 16;   // +32*i rows
    const int brow = tid >> 2, bcol = (tid & 3) * 16;   // +64*i rows
    const float*  apt = A + (size_t)(gy * BM + arow) * K_DIM + kst + (acol >> 2);
    const __half* bpt = g_Bh + (size_t)(gx * BN + brow) * K_DIM + kst + (bcol >> 1);

    const int lm_row  = ((lane >> 4) & 1) * 8 + (lane & 7);
    const int lm_half = ((lane >> 3) & 1) * 8;

    float acc[2][8][4];
    #pragma unroll
    for (int i = 0; i < 2; i++)
        #pragma unroll
        for (int j = 0; j < 8; j++)
            #pragma unroll
            for (int k = 0; k < 4; k++) acc[i][j][k] = 0.f;

    auto load_stage = [&](int s, int kt) {
        char* st = smem + s * ST_BYTES;
        #pragma unroll
        for (int i = 0; i < 4; i++)
            cp_async16(st + (arow + 32 * i) * A_ROW_B + acol,
                       apt + (size_t)32 * i * K_DIM + kt * 32);
        #pragma unroll
        for (int i = 0; i < 2; i++)
            cp_async16(st + A_ST_BYTES + (brow + 64 * i) * B_ROW_B + bcol,
                       bpt + (size_t)64 * i * K_DIM + kt * 32);
    };

    load_stage(0, 0);
    asm volatile("cp.async.commit_group;\n" ::: "memory");
    load_stage(1, 1);
    asm volatile("cp.async.commit_group;\n" ::: "memory");

    const int aoff = (wm * 32 + g) * A_ROW_B + t4 * 8;

    int s_cur = 0, s_load = 2;
    #pragma unroll 1
    for (int kt = 0; kt < NT32; ++kt) {
        asm volatile("cp.async.wait_group 1;\n" ::: "memory");
        __syncthreads();

        if (kt + 2 < NT32) load_stage(s_load, kt + 2);
        asm volatile("cp.async.commit_group;\n" ::: "memory");

        const char* st  = smem + s_cur * ST_BYTES;
        const char* Asb = st + aoff;
        const uint32_t smB = (uint32_t)__cvta_generic_to_shared(st + A_ST_BYTES);

        #pragma unroll
        for (int h = 0; h < 2; h++) {
            uint32_t af[2][4], bf[8][2];
            #pragma unroll
            for (int mi = 0; mi < 2; mi++) {
                const char* p = Asb + mi * 16 * A_ROW_B + h * 64;
                float2 v0 = *(const float2*)(p);
                float2 v1 = *(const float2*)(p + 8 * A_ROW_B);
                float2 v2 = *(const float2*)(p + 32);
                float2 v3 = *(const float2*)(p + 8 * A_ROW_B + 32);
                af[mi][0] = pack_h2(v0.x, v0.y);
                af[mi][1] = pack_h2(v1.x, v1.y);
                af[mi][2] = pack_h2(v2.x, v2.y);
                af[mi][3] = pack_h2(v3.x, v3.y);
            }
            #pragma unroll
            for (int np = 0; np < 4; np++) {
                uint32_t addr = smB + ((wn * 64 + np * 16 + lm_row) * B_ROW_B)
                              + ((h * 16 + lm_half) * 2);
                asm volatile(
                    "ldmatrix.sync.aligned.m8n8.x4.shared.b16 {%0,%1,%2,%3}, [%4];\n"
                    : "=r"(bf[2 * np][0]), "=r"(bf[2 * np][1]),
                      "=r"(bf[2 * np + 1][0]), "=r"(bf[2 * np + 1][1])
                    : "r"(addr));
            }
            #pragma unroll
            for (int mi = 0; mi < 2; mi++)
                #pragma unroll
                for (int ni = 0; ni < 8; ni++) {
                    asm volatile(
                        "mma.sync.aligned.m16n8k16.row.col.f32.f16.f16.f32 "
                        "{%0,%1,%2,%3}, {%4,%5,%6,%7}, {%8,%9}, {%0,%1,%2,%3};\n"
                        : "+f"(acc[mi][ni][0]), "+f"(acc[mi][ni][1]),
                          "+f"(acc[mi][ni][2]), "+f"(acc[mi][ni][3])
                        : "r"(af[mi][0]), "r"(af[mi][1]), "r"(af[mi][2]), "r"(af[mi][3]),
                          "r"(bf[ni][0]), "r"(bf[ni][1]));
                }
        }

        s_cur  = (s_cur  == STAGES - 1) ? 0 : s_cur + 1;
        s_load = (s_load == STAGES - 1) ? 0 : s_load + 1;
    }

    // ---------------- fused epilogue ----------------
    // rows: c0 + wm*32 + mi*16 + g (+8); cols: gx*BN + wn*64 + ni*8 + 2*t4 + p
    #pragma unroll
    for (int ni = 0; ni < 8; ni++) {
        #pragma unroll
        for (int p = 0; p < 2; p++) {
            const int n = gx * BN + wn * 64 + ni * 8 + t4 * 2 + p;
            const float* wdp = Wd + (size_t)n * 256 + c0 + wm * 32 + g;
            float s = 0.f;
            #pragma unroll
            for (int mi = 0; mi < 2; mi++) {
                s += acc[mi][ni][p]     * __ldg(wdp + mi * 16);
                s += acc[mi][ni][2 + p] * __ldg(wdp + mi * 16 + 8);
            }
            s += __shfl_xor_sync(0xffffffffu, s, 16);
            s += __shfl_xor_sync(0xffffffffu, s, 8);
            s += __shfl_xor_sync(0xffffffffu, s, 4);
            if (g == 0)
                atomicAdd(&out[(size_t)b * N_DIM + n], s);
        }
    }
}

extern "C" void kernel_launch(void* const* d_in, const int* in_sizes, int n_in,
                              void* d_out, int out_size) {
    const float* x  = (const float*)d_in[0];  // [8192 x 3136]
    const float* Ws = (const float*)d_in[1];  // [1024 x 3136]
    const float* Wd = (const float*)d_in[2];  // [1024 x 256]
    const float* Wb = (const float*)d_in[3];  // [1024]
    float* out = (float*)d_out;               // [32 x 1024] fp32

    static bool attr_set = false;
    if (!attr_set) {
        cudaFuncSetAttribute(gemm_fused,
                             cudaFuncAttributeMaxDynamicSharedMemorySize, SMEM_BYTES);
        attr_set = true;
    }

    prep_Bh<<<3136, 256>>>(Ws);               // 802816 float4s
    init_out<<<32, 1024>>>(Wb, out);
    dim3 grid(8, 64, 4);                      // 2048 CTAs
    gemm_fused<<<grid, 256, SMEM_BYTES>>>(x, Wd, out);
}

// round 11
// speedup vs baseline: 2.7378x; 1.2365x over previous
#include <cuda_runtime.h>
#include <cuda_fp16.h>
#include <cstdint>

// out[b,n] = sum_{c,hw} x[b,c,hw] * W_s[n,hw] * W_d[n,c] + W_b[n]
// GEMM D[(b,c),n] = x . Ws^T via fp16 mma.sync m16n8k16 (fp32 accum).
// Ws pre-converted fp16. Fused Wd epilogue via atomics (out pre-set to W_b).
// BM=BN=128, 256 thr, 2 CTAs/SM. BK=32, 3 stages. Split-K {800,800,800,736}.
// A rows 160B (conflict-free LDS.64 both phases), B rows 80B (conflict-free ldmatrix).
// Cross-half fragment pipelining to keep HMMA pipe fed at half boundaries.

#define M_DIM 8192
#define N_DIM 1024
#define K_DIM 3136
#define BM 128
#define BN 128
#define STAGES 3
#define A_ROW_B 160                    // 32 floats + 32B pad -> banks 8g+2t4 distinct
#define B_ROW_B 80                     // 32 halfs + 16B pad  -> banks 20r distinct
#define A_ST_BYTES (128 * A_ROW_B)     // 20480
#define B_ST_BYTES (128 * B_ROW_B)     // 10240
#define ST_BYTES   (A_ST_BYTES + B_ST_BYTES)   // 30720
#define SMEM_BYTES (STAGES * ST_BYTES)         // 92160 (x2 CTA = 180KB/SM, fits)

__device__ __align__(16) __half g_Bh[(size_t)N_DIM * K_DIM];  // 6.4 MB fp16 Ws

__device__ __forceinline__ void cp_async16(void* s, const void* g) {
    uint32_t sa = (uint32_t)__cvta_generic_to_shared(s);
    asm volatile("cp.async.cg.shared.global [%0], [%1], 16;\n" :: "r"(sa), "l"(g));
}
__device__ __forceinline__ uint32_t pack_h2(float lo, float hi) {
    __half2 h = __floats2half2_rn(lo, hi);
    return *reinterpret_cast<uint32_t*>(&h);
}

// ---------------- Ws -> fp16 ----------------
__global__ __launch_bounds__(256)
void prep_Bh(const float* __restrict__ Ws) {
    size_t i = (size_t)blockIdx.x * 256 + threadIdx.x;   // 802816 float4s
    float4 v = reinterpret_cast<const float4*>(Ws)[i];
    uint2 o;
    o.x = pack_h2(v.x, v.y);
    o.y = pack_h2(v.z, v.w);
    reinterpret_cast<uint2*>(g_Bh)[i] = o;
}

__global__ __launch_bounds__(1024)
void init_out(const float* __restrict__ Wb, float* __restrict__ out) {
    int i = blockIdx.x * 1024 + threadIdx.x;
    out[i] = Wb[i & (N_DIM - 1)];
}

// ---------------- fused GEMM ----------------
__global__ __launch_bounds__(256, 2)
void gemm_fused(const float* __restrict__ A,
                const float* __restrict__ Wd, float* __restrict__ out) {
    extern __shared__ char smem[];

    const int tid  = threadIdx.x;
    const int warp = tid >> 5;      // 0..7
    const int lane = tid & 31;
    const int wm   = warp & 3;      // 4 warps along M (32 rows)
    const int wn   = warp >> 2;     // 2 warps along N (64 cols)
    const int g    = lane >> 2;
    const int t4   = lane & 3;

    const int gx = blockIdx.x;      // 0..7  N tile
    const int gy = blockIdx.y;      // 0..63 M tile
    const int sp = blockIdx.z;      // 0..3  K split
    const int b  = gy >> 1;
    const int c0 = (gy & 1) * BM;

    const int kst  = sp * 800;
    const int NT32 = (sp == 3) ? 23 : 25;

    const int arow = tid >> 3, acol = (tid & 7) * 16;   // +32*i rows
    const int brow = tid >> 2, bcol = (tid & 3) * 16;   // +64*i rows
    const float*  apt = A + (size_t)(gy * BM + arow) * K_DIM + kst + (acol >> 2);
    const __half* bpt = g_Bh + (size_t)(gx * BN + brow) * K_DIM + kst + (bcol >> 1);

    const int lm_row  = ((lane >> 4) & 1) * 8 + (lane & 7);
    const int lm_half = ((lane >> 3) & 1) * 8;

    float acc[2][8][4];
    #pragma unroll
    for (int i = 0; i < 2; i++)
        #pragma unroll
        for (int j = 0; j < 8; j++)
            #pragma unroll
            for (int k = 0; k < 4; k++) acc[i][j][k] = 0.f;

    auto load_stage = [&](int s, int kt) {
        char* st = smem + s * ST_BYTES;
        #pragma unroll
        for (int i = 0; i < 4; i++)
            cp_async16(st + (arow + 32 * i) * A_ROW_B + acol,
                       apt + (size_t)32 * i * K_DIM + kt * 32);
        #pragma unroll
        for (int i = 0; i < 2; i++)
            cp_async16(st + A_ST_BYTES + (brow + 64 * i) * B_ROW_B + bcol,
                       bpt + (size_t)64 * i * K_DIM + kt * 32);
    };

    load_stage(0, 0);
    asm volatile("cp.async.commit_group;\n" ::: "memory");
    load_stage(1, 1);
    asm volatile("cp.async.commit_group;\n" ::: "memory");

    const int aoff = (wm * 32 + g) * A_ROW_B + t4 * 8;

    int s_cur = 0, s_load = 2;
    #pragma unroll 1
    for (int kt = 0; kt < NT32; ++kt) {
        asm volatile("cp.async.wait_group 1;\n" ::: "memory");
        __syncthreads();

        if (kt + 2 < NT32) load_stage(s_load, kt + 2);
        asm volatile("cp.async.commit_group;\n" ::: "memory");

        const char* st  = smem + s_cur * ST_BYTES;
        const char* Asb = st + aoff;
        const uint32_t smB = (uint32_t)__cvta_generic_to_shared(st + A_ST_BYTES);

        uint32_t af0[2][4], af1[2][4], bf0[8][2], bf1[8][2];

        // ---- h0 B frags ----
        #pragma unroll
        for (int np = 0; np < 4; np++) {
            uint32_t addr = smB + ((wn * 64 + np * 16 + lm_row) * B_ROW_B) + (lm_half * 2);
            asm volatile(
                "ldmatrix.sync.aligned.m8n8.x4.shared.b16 {%0,%1,%2,%3}, [%4];\n"
                : "=r"(bf0[2 * np][0]), "=r"(bf0[2 * np][1]),
                  "=r"(bf0[2 * np + 1][0]), "=r"(bf0[2 * np + 1][1])
                : "r"(addr));
        }
        // ---- h0 A frags ----
        #pragma unroll
        for (int mi = 0; mi < 2; mi++) {
            const char* p = Asb + mi * 16 * A_ROW_B;
            float2 v0 = *(const float2*)(p);
            float2 v1 = *(const float2*)(p + 8 * A_ROW_B);
            float2 v2 = *(const float2*)(p + 32);
            float2 v3 = *(const float2*)(p + 8 * A_ROW_B + 32);
            af0[mi][0] = pack_h2(v0.x, v0.y);
            af0[mi][1] = pack_h2(v1.x, v1.y);
            af0[mi][2] = pack_h2(v2.x, v2.y);
            af0[mi][3] = pack_h2(v3.x, v3.y);
        }
        // ---- h1 B frags issued BEFORE h0 MMAs (keeps tensor pipe fed) ----
        #pragma unroll
        for (int np = 0; np < 4; np++) {
            uint32_t addr = smB + ((wn * 64 + np * 16 + lm_row) * B_ROW_B) + ((16 + lm_half) * 2);
            asm volatile(
                "ldmatrix.sync.aligned.m8n8.x4.shared.b16 {%0,%1,%2,%3}, [%4];\n"
                : "=r"(bf1[2 * np][0]), "=r"(bf1[2 * np][1]),
                  "=r"(bf1[2 * np + 1][0]), "=r"(bf1[2 * np + 1][1])
                : "r"(addr));
        }
        // ---- h0 MMAs ----
        #pragma unroll
        for (int mi = 0; mi < 2; mi++)
            #pragma unroll
            for (int ni = 0; ni < 8; ni++) {
                asm volatile(
                    "mma.sync.aligned.m16n8k16.row.col.f32.f16.f16.f32 "
                    "{%0,%1,%2,%3}, {%4,%5,%6,%7}, {%8,%9}, {%0,%1,%2,%3};\n"
                    : "+f"(acc[mi][ni][0]), "+f"(acc[mi][ni][1]),
                      "+f"(acc[mi][ni][2]), "+f"(acc[mi][ni][3])
                    : "r"(af0[mi][0]), "r"(af0[mi][1]), "r"(af0[mi][2]), "r"(af0[mi][3]),
                      "r"(bf0[ni][0]), "r"(bf0[ni][1]));
            }
        // ---- h1 A frags ----
        #pragma unroll
        for (int mi = 0; mi < 2; mi++) {
            const char* p = Asb + mi * 16 * A_ROW_B + 64;
            float2 v0 = *(const float2*)(p);
            float2 v1 = *(const float2*)(p + 8 * A_ROW_B);
            float2 v2 = *(const float2*)(p + 32);
            float2 v3 = *(const float2*)(p + 8 * A_ROW_B + 32);
            af1[mi][0] = pack_h2(v0.x, v0.y);
            af1[mi][1] = pack_h2(v1.x, v1.y);
            af1[mi][2] = pack_h2(v2.x, v2.y);
            af1[mi][3] = pack_h2(v3.x, v3.y);
        }
        // ---- h1 MMAs ----
        #pragma unroll
        for (int mi = 0; mi < 2; mi++)
            #pragma unroll
            for (int ni = 0; ni < 8; ni++) {
                asm volatile(
                    "mma.sync.aligned.m16n8k16.row.col.f32.f16.f16.f32 "
                    "{%0,%1,%2,%3}, {%4,%5,%6,%7}, {%8,%9}, {%0,%1,%2,%3};\n"
                    : "+f"(acc[mi][ni][0]), "+f"(acc[mi][ni][1]),
                      "+f"(acc[mi][ni][2]), "+f"(acc[mi][ni][3])
                    : "r"(af1[mi][0]), "r"(af1[mi][1]), "r"(af1[mi][2]), "r"(af1[mi][3]),
                      "r"(bf1[ni][0]), "r"(bf1[ni][1]));
            }

        s_cur  = (s_cur  == STAGES - 1) ? 0 : s_cur + 1;
        s_load = (s_load == STAGES - 1) ? 0 : s_load + 1;
    }

    // ---------------- fused epilogue ----------------
    // rows: c0 + wm*32 + mi*16 + g (+8); cols: gx*BN + wn*64 + ni*8 + 2*t4 + p
    #pragma unroll
    for (int ni = 0; ni < 8; ni++) {
        #pragma unroll
        for (int p = 0; p < 2; p++) {
            const int n = gx * BN + wn * 64 + ni * 8 + t4 * 2 + p;
            const float* wdp = Wd + (size_t)n * 256 + c0 + wm * 32 + g;
            float s = 0.f;
            #pragma unroll
            for (int mi = 0; mi < 2; mi++) {
                s += acc[mi][ni][p]     * __ldg(wdp + mi * 16);
                s += acc[mi][ni][2 + p] * __ldg(wdp + mi * 16 + 8);
            }
            s += __shfl_xor_sync(0xffffffffu, s, 16);
            s += __shfl_xor_sync(0xffffffffu, s, 8);
            s += __shfl_xor_sync(0xffffffffu, s, 4);
            if (g == 0)
                atomicAdd(&out[(size_t)b * N_DIM + n], s);
        }
    }
}

extern "C" void kernel_launch(void* const* d_in, const int* in_sizes, int n_in,
                              void* d_out, int out_size) {
    const float* x  = (const float*)d_in[0];  // [8192 x 3136]
    const float* Ws = (const float*)d_in[1];  // [1024 x 3136]
    const float* Wd = (const float*)d_in[2];  // [1024 x 256]
    const float* Wb = (const float*)d_in[3];  // [1024]
    float* out = (float*)d_out;               // [32 x 1024] fp32

    static bool attr_set = false;
    if (!attr_set) {
        cudaFuncSetAttribute(gemm_fused,
                             cudaFuncAttributeMaxDynamicSharedMemorySize, SMEM_BYTES);
        attr_set = true;
    }

    prep_Bh<<<3136, 256>>>(Ws);               // 802816 float4s
    init_out<<<32, 1024>>>(Wb, out);
    dim3 grid(8, 64, 4);                      // 2048 CTAs
    gemm_fused<<<grid, 256, SMEM_BYTES>>>(x, Wd, out);
}